// round 15
// baseline (speedup 1.0000x reference)
#include <cuda_runtime.h>
#include <cuda_bf16.h>
#include <mma.h>
#include <cstdint>

using namespace nvcuda;

#define B_   2
#define L_   2048
#define D_   1024
#define H_   16
#define DH_  64
#define M_   (B_*L_)          // 4096 rows
#define K2_  2048             // split-K (hi/lo interleaved)
#define SCALE 0.125f          // 1/sqrt(64)

// ---------------- scratch (static device memory; no allocs) ----------------
__device__ float g_v[M_*D_];
__device__ __nv_bfloat16 g_xs [M_*K2_];
__device__ __nv_bfloat16 g_cs [M_*K2_];
__device__ __nv_bfloat16 g_wqs[D_*K2_];   // weights, (hi,lo) interleaved
__device__ __nv_bfloat16 g_wks[D_*K2_];
__device__ __nv_bfloat16 g_wvs[D_*K2_];
__device__ __nv_bfloat16 g_wos[D_*K2_];
__device__ __nv_bfloat16 g_wqw[D_*K2_];   // weights, (lo,hi) swapped
__device__ __nv_bfloat16 g_wkw[D_*K2_];
__device__ __nv_bfloat16 g_wvw[D_*K2_];
__device__ __nv_bfloat16 g_wow[D_*K2_];
// attention split operands
__device__ __nv_bfloat16 g_qs [(size_t)B_*H_*L_*128];   // Q*scale (hi,lo)
__device__ __nv_bfloat16 g_qsw[(size_t)B_*H_*L_*128];   // Q*scale (lo,hi)
__device__ __nv_bfloat16 g_ks [(size_t)B_*H_*L_*128];   // K (hi,lo)
__device__ __nv_bfloat16 g_vs [(size_t)B_*H_*DH_*2*L_]; // V^T (hi,lo along key)

// ---------------- hi/lo bf16 pair packing ----------------
__device__ __forceinline__ uint32_t pack_hl(float x) {
    __nv_bfloat16 h = __float2bfloat16(x);
    __nv_bfloat16 l = __float2bfloat16(x - __bfloat162float(h));
    return (uint32_t)__bfloat16_as_ushort(h) |
           ((uint32_t)__bfloat16_as_ushort(l) << 16);
}
__device__ __forceinline__ uint32_t pack_lh(float x) {
    __nv_bfloat16 h = __float2bfloat16(x);
    __nv_bfloat16 l = __float2bfloat16(x - __bfloat162float(h));
    return (uint32_t)__bfloat16_as_ushort(l) |
           ((uint32_t)__bfloat16_as_ushort(h) << 16);
}

// ---------------- split kernels (inputs) ----------------
__global__ __launch_bounds__(256)
void split_x(const float* __restrict__ src, int n4)
{
    int i = blockIdx.x * 256 + threadIdx.x;
    if (i >= n4) return;
    float4 v = ((const float4*)src)[i];
    uint4 o;
    o.x = pack_hl(v.x); o.y = pack_hl(v.y); o.z = pack_hl(v.z); o.w = pack_hl(v.w);
    ((uint4*)g_xs)[i] = o;
}

__global__ __launch_bounds__(256)
void split_w(const float* __restrict__ src, int tag, int n4)
{
    __nv_bfloat16* dn = tag == 0 ? g_wqs : tag == 1 ? g_wks : tag == 2 ? g_wvs : g_wos;
    __nv_bfloat16* ds = tag == 0 ? g_wqw : tag == 1 ? g_wkw : tag == 2 ? g_wvw : g_wow;
    int i = blockIdx.x * 256 + threadIdx.x;
    if (i >= n4) return;
    float4 v = ((const float4*)src)[i];
    uint4 on, os;
    on.x = pack_hl(v.x); os.x = pack_lh(v.x);
    on.y = pack_hl(v.y); os.y = pack_lh(v.y);
    on.z = pack_hl(v.z); os.z = pack_lh(v.z);
    on.w = pack_hl(v.w); os.w = pack_lh(v.w);
    ((uint4*)dn)[i] = on;
    ((uint4*)ds)[i] = os;
}

// V transpose + split along key: g_v [bh][l][d] -> g_vs [bh][d][2l]
__global__ __launch_bounds__(256)
void v_split()
{
    __shared__ float tile[128 * 65];
    const int lb = blockIdx.x;
    const int bh = blockIdx.y;
    const int tid = threadIdx.x;
    const float* src = g_v + ((size_t)bh * L_ + lb * 128) * DH_;
    for (int i = 0; i < 8; i++) {
        int u = tid + i * 256;
        int r = u >> 4, q = u & 15;
        float4 t = ((const float4*)(src + (size_t)r * DH_))[q];
        tile[r * 65 + q * 4 + 0] = t.x;
        tile[r * 65 + q * 4 + 1] = t.y;
        tile[r * 65 + q * 4 + 2] = t.z;
        tile[r * 65 + q * 4 + 3] = t.w;
    }
    __syncthreads();
    const int d = tid >> 2, part = tid & 3;
    uint32_t* dst = (uint32_t*)g_vs + ((size_t)bh * DH_ + d) * L_
                    + lb * 128 + part * 32;
    #pragma unroll
    for (int j = 0; j < 32; j++) {
        float val = tile[(part * 32 + j) * 65 + d];
        dst[j] = pack_hl(val);
    }
}

// ---------------- WMMA GEMM (projections) — register-prefetch pipeline -----
#define TM 128
#define TN 128
#define BK 32
#define NCH (K2_ / BK)        // 64
#define AS 40
#define STG 20

__global__ __launch_bounds__(256)
void mma_gemm(int which,
              const float* __restrict__ bi0, const float* __restrict__ bi1,
              const float* __restrict__ bi2, float* __restrict__ out_dst)
{
    __shared__ __align__(16) __nv_bfloat16 sA [TM * AS];
    __shared__ __align__(16) __nv_bfloat16 sBn[TN * AS];
    __shared__ __align__(16) __nv_bfloat16 sBw[TN * AS];
    __shared__ __align__(16) float stage[8][16 * STG];

    const int mat = blockIdx.z;
    const __nv_bfloat16* A = (which == 0) ? g_xs : g_cs;
    const __nv_bfloat16* Bn =
        (which == 1) ? g_wos : (mat == 0 ? g_wqs : (mat == 1 ? g_wks : g_wvs));
    const __nv_bfloat16* Bw =
        (which == 1) ? g_wow : (mat == 0 ? g_wqw : (mat == 1 ? g_wkw : g_wvw));
    const float* bias = (mat == 0) ? bi0 : (mat == 1 ? bi1 : bi2);

    const int row0 = blockIdx.x * TM;
    const int col0 = blockIdx.y * TN;
    const int tid  = threadIdx.x;
    const int wid  = tid >> 5, lane = tid & 31;
    const int wr   = wid >> 2;
    const int wc   = wid & 3;

    wmma::fragment<wmma::accumulator, 16, 16, 16, float> acc[4][2];
    #pragma unroll
    for (int i = 0; i < 4; i++)
        #pragma unroll
        for (int j = 0; j < 2; j++)
            wmma::fill_fragment(acc[i][j], 0.0f);

    const int r0c = tid >> 2,          q0c = tid & 3;
    const int r1c = (tid + 256) >> 2,  q1c = (tid + 256) & 3;

    const __nv_bfloat16* pA0 = A  + (size_t)(row0 + r0c) * K2_ + q0c * 8;
    const __nv_bfloat16* pA1 = A  + (size_t)(row0 + r1c) * K2_ + q1c * 8;
    const __nv_bfloat16* pN0 = Bn + (size_t)(col0 + r0c) * K2_ + q0c * 8;
    const __nv_bfloat16* pN1 = Bn + (size_t)(col0 + r1c) * K2_ + q1c * 8;
    const __nv_bfloat16* pW0 = Bw + (size_t)(col0 + r0c) * K2_ + q0c * 8;
    const __nv_bfloat16* pW1 = Bw + (size_t)(col0 + r1c) * K2_ + q1c * 8;

    // preload chunk 0 into registers
    uint4 rA0 = *(const uint4*)pA0, rA1 = *(const uint4*)pA1;
    uint4 rN0 = *(const uint4*)pN0, rN1 = *(const uint4*)pN1;
    uint4 rW0 = *(const uint4*)pW0, rW1 = *(const uint4*)pW1;

    for (int ch = 0; ch < NCH; ch++) {
        __syncthreads();          // prev compute done (smem reuse safe)
        *(uint4*)&sA [r0c * AS + q0c * 8] = rA0;
        *(uint4*)&sA [r1c * AS + q1c * 8] = rA1;
        *(uint4*)&sBn[r0c * AS + q0c * 8] = rN0;
        *(uint4*)&sBn[r1c * AS + q1c * 8] = rN1;
        *(uint4*)&sBw[r0c * AS + q0c * 8] = rW0;
        *(uint4*)&sBw[r1c * AS + q1c * 8] = rW1;
        __syncthreads();

        if (ch + 1 < NCH) {       // issue next chunk loads; latency hidden by MMAs
            const size_t ko = (size_t)(ch + 1) * BK;
            rA0 = *(const uint4*)(pA0 + ko); rA1 = *(const uint4*)(pA1 + ko);
            rN0 = *(const uint4*)(pN0 + ko); rN1 = *(const uint4*)(pN1 + ko);
            rW0 = *(const uint4*)(pW0 + ko); rW1 = *(const uint4*)(pW1 + ko);
        }

        #pragma unroll
        for (int kk = 0; kk < 2; kk++) {
            const int k0 = kk * 16;
            wmma::fragment<wmma::matrix_a, 16, 16, 16, __nv_bfloat16,
                           wmma::row_major> af[4];
            #pragma unroll
            for (int i = 0; i < 4; i++)
                wmma::load_matrix_sync(af[i], &sA[(wr * 64 + i * 16) * AS + k0], AS);
            wmma::fragment<wmma::matrix_b, 16, 16, 16, __nv_bfloat16,
                           wmma::col_major> bfn[2], bfw[2];
            #pragma unroll
            for (int j = 0; j < 2; j++) {
                wmma::load_matrix_sync(bfn[j], &sBn[(wc * 32 + j * 16) * AS + k0], AS);
                wmma::load_matrix_sync(bfw[j], &sBw[(wc * 32 + j * 16) * AS + k0], AS);
            }
            #pragma unroll
            for (int i = 0; i < 4; i++)
                #pragma unroll
                for (int j = 0; j < 2; j++) {
                    wmma::mma_sync(acc[i][j], af[i], bfn[j], acc[i][j]);
                    wmma::mma_sync(acc[i][j], af[i], bfw[j], acc[i][j]);
                }
        }
    }

    // ---- epilogue: bias add + destination-specific packing ----
    __syncthreads();
    #pragma unroll
    for (int i = 0; i < 4; i++) {
        #pragma unroll
        for (int j = 0; j < 2; j++) {
            wmma::store_matrix_sync(&stage[wid][0], acc[i][j], STG,
                                    wmma::mem_row_major);
            __syncwarp();
            #pragma unroll
            for (int e = 0; e < 8; e++) {
                int idx = lane * 8 + e;
                int rr = idx >> 4, cc = idx & 15;
                int m = row0 + wr * 64 + i * 16 + rr;
                int n = col0 + wc * 32 + j * 16 + cc;
                float v = stage[wid][rr * STG + cc] + bias[n];
                if (which == 1) {
                    out_dst[(size_t)m * D_ + n] = v;
                } else {
                    int l = m & (L_ - 1), bb = m >> 11;
                    int h = n >> 6, d = n & 63;
                    size_t hrow = ((size_t)(bb * H_ + h) * L_ + l);
                    if (mat == 0) {
                        float w = v * SCALE;
                        ((uint32_t*)g_qs )[hrow * 64 + d] = pack_hl(w);
                        ((uint32_t*)g_qsw)[hrow * 64 + d] = pack_lh(w);
                    } else if (mat == 1) {
                        ((uint32_t*)g_ks)[hrow * 64 + d] = pack_hl(v);
                    } else {
                        g_v[hrow * DH_ + d] = v;
                    }
                }
            }
            __syncwarp();
        }
    }
}

// ---------------- WMMA attention — 16 q-rows/CTA, register-prefetch --------
// smem: bB | bAn | bAw | red  = ~60KB -> 3 CTAs/SM
#define QB2  16
#define LD_K 136
#define LD_V 264
#define OFF_AN   34816
#define OFF_AW   (OFF_AN + QB2*LD_V*2)   // 43264
#define OFF_RED  (OFF_AW + QB2*LD_V*2)   // 51712
#define SM2_BYTES (OFF_RED + 8192)       // 59904

__global__ __launch_bounds__(256)
void attn_wmma(float* __restrict__ attn_out)
{
    extern __shared__ char smraw[];
    __nv_bfloat16* bB  = (__nv_bfloat16*)smraw;
    __nv_bfloat16* bAn = (__nv_bfloat16*)(smraw + OFF_AN);
    __nv_bfloat16* bAw = (__nv_bfloat16*)(smraw + OFF_AW);
    float* red = (float*)(smraw + OFF_RED);

    const int q0 = blockIdx.x * QB2;
    const int hh = blockIdx.y, bb = blockIdx.z;
    const int tid = threadIdx.x, wid = tid >> 5, lane = tid & 31;
    const int bh = bb * H_ + hh;

    const __nv_bfloat16* Qn = g_qs  + ((size_t)bh * L_ + q0) * 128;
    const __nv_bfloat16* Qw = g_qsw + ((size_t)bh * L_ + q0) * 128;
    const __nv_bfloat16* Kh = g_ks  + (size_t)bh * L_ * 128;
    const __nv_bfloat16* Vt = g_vs  + (size_t)bh * DH_ * (2 * L_);
    float* gW = attn_out + ((size_t)bh * L_ + q0) * L_;   // 16 x 2048 block

    // load Q tiles (16 x 128 bf16 each) into bAn/bAw, ldm LD_K
    for (int u = tid; u < 512; u += 256) {
        int half = u >> 8;
        int v = u & 255;
        int r = v >> 4, q = v & 15;
        uint4 src = ((const uint4*)((half ? Qw : Qn) + r * 128))[q];
        __nv_bfloat16* dst = half ? bAw : bAn;
        *(uint4*)(dst + r * LD_K + q * 8) = src;
    }

    // ---- phase 1: scores -> attn_out (raw), K-chunk register prefetch ----
    {
        wmma::fragment<wmma::accumulator, 16, 16, 16, float> sacc;
        const int r_ld = tid >> 4, q_ld = tid & 15;   // row group, quad
        // preload chunk 0: thread covers rows r_ld, r_ld+16, ..., r_ld+112
        uint4 pk[8];
        #pragma unroll
        for (int i = 0; i < 8; i++)
            pk[i] = ((const uint4*)(Kh + (size_t)(r_ld + i * 16) * 128))[q_ld];

        for (int kc = 0; kc < L_; kc += 128) {
            __syncthreads();
            #pragma unroll
            for (int i = 0; i < 8; i++)
                *(uint4*)(bB + (r_ld + i * 16) * LD_K + q_ld * 8) = pk[i];
            __syncthreads();
            if (kc + 128 < L_) {
                #pragma unroll
                for (int i = 0; i < 8; i++)
                    pk[i] = ((const uint4*)(Kh +
                        (size_t)(kc + 128 + r_ld + i * 16) * 128))[q_ld];
            }
            wmma::fill_fragment(sacc, 0.0f);
            #pragma unroll
            for (int kt = 0; kt < 8; kt++) {
                wmma::fragment<wmma::matrix_a, 16, 16, 16, __nv_bfloat16,
                               wmma::row_major> a;
                wmma::fragment<wmma::matrix_b, 16, 16, 16, __nv_bfloat16,
                               wmma::col_major> b;
                wmma::load_matrix_sync(b, bB + (size_t)wid * 16 * LD_K + kt * 16, LD_K);
                wmma::load_matrix_sync(a, bAn + kt * 16, LD_K);
                wmma::mma_sync(sacc, a, b, sacc);
                wmma::load_matrix_sync(a, bAw + kt * 16, LD_K);
                wmma::mma_sync(sacc, a, b, sacc);
            }
            wmma::store_matrix_sync(gW + kc + wid * 16, sacc, L_,
                                    wmma::mem_row_major);
        }
    }
    __syncthreads();

    // ---- phase 2: softmax in gmem (L2-hot) ----
    for (int r = wid; r < QB2; r += 8) {
        float* row = gW + (size_t)r * L_;
        float m = -1e30f;
        for (int k = lane; k < L_; k += 32) m = fmaxf(m, row[k]);
        #pragma unroll
        for (int o = 16; o; o >>= 1) m = fmaxf(m, __shfl_xor_sync(0xffffffffu, m, o));
        float s = 0.f;
        for (int k = lane; k < L_; k += 32) {
            float e = __expf(row[k] - m);
            row[k] = e;
            s += e;
        }
        #pragma unroll
        for (int o = 16; o; o >>= 1) s += __shfl_xor_sync(0xffffffffu, s, o);
        float inv = 1.f / s;
        for (int k = lane; k < L_; k += 32)
            row[k] = row[k] * inv;
    }
    __syncthreads();

    // ---- phase 3: ctx = W @ V, Vt+W register prefetch, pack into g_cs ----
    {
        wmma::fragment<wmma::accumulator, 16, 16, 16, float> cacc;
        wmma::fill_fragment(cacc, 0.0f);
        const int nt = wid >> 1, kh = wid & 1;
        const int wr2 = tid >> 4, wks = (tid & 15) * 8;
        const int r_ld = tid >> 5, q_ld = tid & 31;   // Vt: 64 rows x 32 quads

        // preload chunk 0
        uint4 pv[8];
        float wf[8];
        #pragma unroll
        for (int i = 0; i < 8; i++)
            pv[i] = ((const uint4*)(Vt + (size_t)(r_ld + i * 8) * (2 * L_)))[q_ld];
        {
            const float* srow = gW + (size_t)wr2 * L_ + wks;
            #pragma unroll
            for (int j = 0; j < 8; j++) wf[j] = srow[j];
        }

        for (int c = 0; c < 16; c++) {               // 16 chunks x 128 keys
            __syncthreads();
            #pragma unroll
            for (int i = 0; i < 8; i++)
                *(uint4*)(bB + (r_ld + i * 8) * LD_V + q_ld * 8) = pv[i];
            {
                uint32_t* wn = (uint32_t*)bAn + wr2 * (LD_V / 2) + wks;
                uint32_t* ww = (uint32_t*)bAw + wr2 * (LD_V / 2) + wks;
                #pragma unroll
                for (int j = 0; j < 8; j++) {
                    wn[j] = pack_hl(wf[j]);
                    ww[j] = pack_lh(wf[j]);
                }
            }
            __syncthreads();
            if (c + 1 < 16) {
                #pragma unroll
                for (int i = 0; i < 8; i++)
                    pv[i] = ((const uint4*)(Vt + (size_t)(r_ld + i * 8) * (2 * L_)
                                            + (c + 1) * 256))[q_ld];
                const float* srow = gW + (size_t)wr2 * L_ + (c + 1) * 128 + wks;
                #pragma unroll
                for (int j = 0; j < 8; j++) wf[j] = srow[j];
            }
            #pragma unroll
            for (int kt = 0; kt < 8; kt++) {
                int k0 = kh * 128 + kt * 16;
                wmma::fragment<wmma::matrix_a, 16, 16, 16, __nv_bfloat16,
                               wmma::row_major> a;
                wmma::fragment<wmma::matrix_b, 16, 16, 16, __nv_bfloat16,
                               wmma::col_major> b;
                wmma::load_matrix_sync(b, bB + (size_t)nt * 16 * LD_V + k0, LD_V);
                wmma::load_matrix_sync(a, bAn + k0, LD_V);
                wmma::mma_sync(cacc, a, b, cacc);
                wmma::load_matrix_sync(a, bAw + k0, LD_V);
                wmma::mma_sync(cacc, a, b, cacc);
            }
        }
        __syncthreads();
        wmma::store_matrix_sync(red + wid * 256, cacc, 16, wmma::mem_row_major);
        __syncthreads();
        for (int e = tid; e < QB2 * 64; e += 256) {
            int m = e >> 6, col = e & 63;
            int w0 = (col >> 4) << 1;
            float v = red[w0 * 256 + m * 16 + (col & 15)]
                    + red[(w0 + 1) * 256 + m * 16 + (col & 15)];
            size_t row = (size_t)bb * L_ + q0 + m;
            ((uint32_t*)g_cs)[row * 1024 + hh * 64 + col] = pack_hl(v);
        }
    }
}

// ---------------- launch ----------------
extern "C" void kernel_launch(void* const* d_in, const int* in_sizes, int n_in,
                              void* d_out, int out_size)
{
    const float* x  = (const float*)d_in[0];
    const float* Wq = (const float*)d_in[1];
    const float* bq = (const float*)d_in[2];
    const float* Wk = (const float*)d_in[3];
    const float* bk = (const float*)d_in[4];
    const float* Wv = (const float*)d_in[5];
    const float* bv = (const float*)d_in[6];
    const float* Wo = (const float*)d_in[7];
    const float* bo = (const float*)d_in[8];

    float* out  = (float*)d_out;                       // [B, L, D]
    float* attn = out + (size_t)M_ * D_;               // [B, H, L, L]

    cudaFuncSetAttribute(attn_wmma,
                         cudaFuncAttributeMaxDynamicSharedMemorySize, SM2_BYTES);

    // split projection inputs
    {
        int n4x = M_ * D_ / 4;
        int n4w = D_ * D_ / 4;
        split_x<<<(n4x + 255) / 256, 256>>>(x, n4x);
        split_w<<<(n4w + 255) / 256, 256>>>(Wq, 0, n4w);
        split_w<<<(n4w + 255) / 256, 256>>>(Wk, 1, n4w);
        split_w<<<(n4w + 255) / 256, 256>>>(Wv, 2, n4w);
        split_w<<<(n4w + 255) / 256, 256>>>(Wo, 3, n4w);
    }

    // QKV projections (epilogue writes split Q/K directly; V as float)
    dim3 gq(M_ / TM, D_ / TN, 3);
    mma_gemm<<<gq, 256>>>(0, bq, bk, bv, nullptr);

    // V transpose+split
    dim3 gv(L_ / 128, B_ * H_);
    v_split<<<gv, 256>>>();

    // attention (epilogue packs ctx straight into g_cs)
    dim3 ga(L_ / QB2, H_, B_);
    attn_wmma<<<ga, 256, SM2_BYTES>>>(attn);

    // output projection
    dim3 go(M_ / TM, D_ / TN, 1);
    mma_gemm<<<go, 256>>>(1, bo, bo, bo, out);
}

// round 16
// speedup vs baseline: 1.0404x; 1.0404x over previous
#include <cuda_runtime.h>
#include <cuda_bf16.h>
#include <mma.h>
#include <cstdint>

using namespace nvcuda;

#define B_   2
#define L_   2048
#define D_   1024
#define H_   16
#define DH_  64
#define M_   (B_*L_)          // 4096 rows
#define K2_  2048             // split-K (hi/lo interleaved)
#define SCALE 0.125f          // 1/sqrt(64)

// ---------------- scratch (static device memory; no allocs) ----------------
__device__ float g_v[M_*D_];
__device__ __nv_bfloat16 g_xs [M_*K2_];
__device__ __nv_bfloat16 g_cs [M_*K2_];
__device__ __nv_bfloat16 g_wqs[D_*K2_];   // weights, (hi,lo) interleaved
__device__ __nv_bfloat16 g_wks[D_*K2_];
__device__ __nv_bfloat16 g_wvs[D_*K2_];
__device__ __nv_bfloat16 g_wos[D_*K2_];
__device__ __nv_bfloat16 g_wqw[D_*K2_];   // weights, (lo,hi) swapped
__device__ __nv_bfloat16 g_wkw[D_*K2_];
__device__ __nv_bfloat16 g_wvw[D_*K2_];
__device__ __nv_bfloat16 g_wow[D_*K2_];
// attention split operands
__device__ __nv_bfloat16 g_qs [(size_t)B_*H_*L_*128];   // Q*scale (hi,lo)
__device__ __nv_bfloat16 g_qsw[(size_t)B_*H_*L_*128];   // Q*scale (lo,hi)
__device__ __nv_bfloat16 g_ks [(size_t)B_*H_*L_*128];   // K (hi,lo)
__device__ __nv_bfloat16 g_vs [(size_t)B_*H_*DH_*2*L_]; // V^T (hi,lo along key)

// ---------------- helpers ----------------
__device__ __forceinline__ uint32_t smem_u32(const void* p) {
    uint32_t a;
    asm("{ .reg .u64 t; cvta.to.shared.u64 t, %1; cvt.u32.u64 %0, t; }"
        : "=r"(a) : "l"(p));
    return a;
}
#define CP_ASYNC16(dst, src) \
    asm volatile("cp.async.cg.shared.global [%0], [%1], 16;" :: "r"(dst), "l"(src))
#define CP_COMMIT() asm volatile("cp.async.commit_group;" ::: "memory")
#define CP_WAIT(n)  asm volatile("cp.async.wait_group %0;" :: "n"(n) : "memory")

__device__ __forceinline__ uint32_t pack_hl(float x) {
    __nv_bfloat16 h = __float2bfloat16(x);
    __nv_bfloat16 l = __float2bfloat16(x - __bfloat162float(h));
    return (uint32_t)__bfloat16_as_ushort(h) |
           ((uint32_t)__bfloat16_as_ushort(l) << 16);
}
__device__ __forceinline__ uint32_t pack_lh(float x) {
    __nv_bfloat16 h = __float2bfloat16(x);
    __nv_bfloat16 l = __float2bfloat16(x - __bfloat162float(h));
    return (uint32_t)__bfloat16_as_ushort(l) |
           ((uint32_t)__bfloat16_as_ushort(h) << 16);
}

// ---------------- split kernels (inputs) ----------------
__global__ __launch_bounds__(256)
void split_x(const float* __restrict__ src, int n4)
{
    int i = blockIdx.x * 256 + threadIdx.x;
    if (i >= n4) return;
    float4 v = ((const float4*)src)[i];
    uint4 o;
    o.x = pack_hl(v.x); o.y = pack_hl(v.y); o.z = pack_hl(v.z); o.w = pack_hl(v.w);
    ((uint4*)g_xs)[i] = o;
}

__global__ __launch_bounds__(256)
void split_w(const float* __restrict__ src, int tag, int n4)
{
    __nv_bfloat16* dn = tag == 0 ? g_wqs : tag == 1 ? g_wks : tag == 2 ? g_wvs : g_wos;
    __nv_bfloat16* ds = tag == 0 ? g_wqw : tag == 1 ? g_wkw : tag == 2 ? g_wvw : g_wow;
    int i = blockIdx.x * 256 + threadIdx.x;
    if (i >= n4) return;
    float4 v = ((const float4*)src)[i];
    uint4 on, os;
    on.x = pack_hl(v.x); os.x = pack_lh(v.x);
    on.y = pack_hl(v.y); os.y = pack_lh(v.y);
    on.z = pack_hl(v.z); os.z = pack_lh(v.z);
    on.w = pack_hl(v.w); os.w = pack_lh(v.w);
    ((uint4*)dn)[i] = on;
    ((uint4*)ds)[i] = os;
}

// V transpose + split along key: g_v [bh][l][d] -> g_vs [bh][d][2l]
__global__ __launch_bounds__(256)
void v_split()
{
    __shared__ float tile[128 * 65];
    const int lb = blockIdx.x;
    const int bh = blockIdx.y;
    const int tid = threadIdx.x;
    const float* src = g_v + ((size_t)bh * L_ + lb * 128) * DH_;
    for (int i = 0; i < 8; i++) {
        int u = tid + i * 256;
        int r = u >> 4, q = u & 15;
        float4 t = ((const float4*)(src + (size_t)r * DH_))[q];
        tile[r * 65 + q * 4 + 0] = t.x;
        tile[r * 65 + q * 4 + 1] = t.y;
        tile[r * 65 + q * 4 + 2] = t.z;
        tile[r * 65 + q * 4 + 3] = t.w;
    }
    __syncthreads();
    const int d = tid >> 2, part = tid & 3;
    uint32_t* dst = (uint32_t*)g_vs + ((size_t)bh * DH_ + d) * L_
                    + lb * 128 + part * 32;
    #pragma unroll
    for (int j = 0; j < 32; j++) {
        float val = tile[(part * 32 + j) * 65 + d];
        dst[j] = pack_hl(val);
    }
}

// ---------------- WMMA GEMM — cp.async 2-stage double buffer ----------------
#define TM 128
#define TN 128
#define BK 32
#define NCH (K2_ / BK)        // 64
#define AS 40
#define STG 20
// dynamic smem layout (bytes): sA[2] | sBn[2] | sBw[2] | stage
#define GT   (TM * AS * 2)               // one tile: 10240 B
#define G_A(s)   ((s) * GT)
#define G_BN(s)  (2 * GT + (s) * GT)
#define G_BW(s)  (4 * GT + (s) * GT)
#define G_STG    (6 * GT)                // 61440
#define GSM_BYTES (G_STG + 8 * 16 * STG * 4)   // 71680

__global__ __launch_bounds__(256)
void mma_gemm(int which,
              const float* __restrict__ bi0, const float* __restrict__ bi1,
              const float* __restrict__ bi2, float* __restrict__ out_dst)
{
    extern __shared__ char gsm[];
    float* stage = (float*)(gsm + G_STG);

    const int mat = blockIdx.z;
    const __nv_bfloat16* A = (which == 0) ? g_xs : g_cs;
    const __nv_bfloat16* Bn =
        (which == 1) ? g_wos : (mat == 0 ? g_wqs : (mat == 1 ? g_wks : g_wvs));
    const __nv_bfloat16* Bw =
        (which == 1) ? g_wow : (mat == 0 ? g_wqw : (mat == 1 ? g_wkw : g_wvw));
    const float* bias = (mat == 0) ? bi0 : (mat == 1 ? bi1 : bi2);

    const int row0 = blockIdx.x * TM;
    const int col0 = blockIdx.y * TN;
    const int tid  = threadIdx.x;
    const int wid  = tid >> 5, lane = tid & 31;
    const int wr   = wid >> 2;
    const int wc   = wid & 3;

    wmma::fragment<wmma::accumulator, 16, 16, 16, float> acc[4][2];
    #pragma unroll
    for (int i = 0; i < 4; i++)
        #pragma unroll
        for (int j = 0; j < 2; j++)
            wmma::fill_fragment(acc[i][j], 0.0f);

    // cp.async distribution: rows r0c and r0c+64, 16B quad q0c
    const int r0c = tid >> 2, q0c = tid & 3;
    const int r1c = r0c + 64;

    const __nv_bfloat16* pA0 = A  + (size_t)(row0 + r0c) * K2_ + q0c * 8;
    const __nv_bfloat16* pA1 = A  + (size_t)(row0 + r1c) * K2_ + q0c * 8;
    const __nv_bfloat16* pN0 = Bn + (size_t)(col0 + r0c) * K2_ + q0c * 8;
    const __nv_bfloat16* pN1 = Bn + (size_t)(col0 + r1c) * K2_ + q0c * 8;
    const __nv_bfloat16* pW0 = Bw + (size_t)(col0 + r0c) * K2_ + q0c * 8;
    const __nv_bfloat16* pW1 = Bw + (size_t)(col0 + r1c) * K2_ + q0c * 8;

    const uint32_t smem0 = smem_u32(gsm);
    const uint32_t off0 = (uint32_t)(r0c * AS + q0c * 8) * 2;
    const uint32_t off1 = (uint32_t)(r1c * AS + q0c * 8) * 2;

    // issue chunk 0
    {
        CP_ASYNC16(smem0 + G_A(0)  + off0, pA0);
        CP_ASYNC16(smem0 + G_A(0)  + off1, pA1);
        CP_ASYNC16(smem0 + G_BN(0) + off0, pN0);
        CP_ASYNC16(smem0 + G_BN(0) + off1, pN1);
        CP_ASYNC16(smem0 + G_BW(0) + off0, pW0);
        CP_ASYNC16(smem0 + G_BW(0) + off1, pW1);
        CP_COMMIT();
    }

    for (int ch = 0; ch < NCH; ch++) {
        const int st = ch & 1;
        if (ch + 1 < NCH) {
            const size_t ko = (size_t)(ch + 1) * BK;
            const int ns = st ^ 1;
            CP_ASYNC16(smem0 + G_A(ns)  + off0, pA0 + ko);
            CP_ASYNC16(smem0 + G_A(ns)  + off1, pA1 + ko);
            CP_ASYNC16(smem0 + G_BN(ns) + off0, pN0 + ko);
            CP_ASYNC16(smem0 + G_BN(ns) + off1, pN1 + ko);
            CP_ASYNC16(smem0 + G_BW(ns) + off0, pW0 + ko);
            CP_ASYNC16(smem0 + G_BW(ns) + off1, pW1 + ko);
            CP_COMMIT();
            CP_WAIT(1);           // chunk ch resident; ch+1 still in flight
        } else {
            CP_WAIT(0);
        }
        __syncthreads();

        const __nv_bfloat16* sA  = (const __nv_bfloat16*)(gsm + G_A(st));
        const __nv_bfloat16* sBn = (const __nv_bfloat16*)(gsm + G_BN(st));
        const __nv_bfloat16* sBw = (const __nv_bfloat16*)(gsm + G_BW(st));

        #pragma unroll
        for (int kk = 0; kk < 2; kk++) {
            const int k0 = kk * 16;
            wmma::fragment<wmma::matrix_a, 16, 16, 16, __nv_bfloat16,
                           wmma::row_major> af[4];
            #pragma unroll
            for (int i = 0; i < 4; i++)
                wmma::load_matrix_sync(af[i], &sA[(wr * 64 + i * 16) * AS + k0], AS);
            wmma::fragment<wmma::matrix_b, 16, 16, 16, __nv_bfloat16,
                           wmma::col_major> bfn[2], bfw[2];
            #pragma unroll
            for (int j = 0; j < 2; j++) {
                wmma::load_matrix_sync(bfn[j], &sBn[(wc * 32 + j * 16) * AS + k0], AS);
                wmma::load_matrix_sync(bfw[j], &sBw[(wc * 32 + j * 16) * AS + k0], AS);
            }
            #pragma unroll
            for (int i = 0; i < 4; i++)
                #pragma unroll
                for (int j = 0; j < 2; j++) {
                    wmma::mma_sync(acc[i][j], af[i], bfn[j], acc[i][j]);
                    wmma::mma_sync(acc[i][j], af[i], bfw[j], acc[i][j]);
                }
        }
        __syncthreads();
    }

    // ---- epilogue: bias add + destination-specific packing ----
    #pragma unroll
    for (int i = 0; i < 4; i++) {
        #pragma unroll
        for (int j = 0; j < 2; j++) {
            wmma::store_matrix_sync(&stage[wid * 16 * STG], acc[i][j], STG,
                                    wmma::mem_row_major);
            __syncwarp();
            #pragma unroll
            for (int e = 0; e < 8; e++) {
                int idx = lane * 8 + e;
                int rr = idx >> 4, cc = idx & 15;
                int m = row0 + wr * 64 + i * 16 + rr;
                int n = col0 + wc * 32 + j * 16 + cc;
                float v = stage[wid * 16 * STG + rr * STG + cc] + bias[n];
                if (which == 1) {
                    out_dst[(size_t)m * D_ + n] = v;
                } else {
                    int l = m & (L_ - 1), bb = m >> 11;
                    int h = n >> 6, d = n & 63;
                    size_t hrow = ((size_t)(bb * H_ + h) * L_ + l);
                    if (mat == 0) {
                        float w = v * SCALE;
                        ((uint32_t*)g_qs )[hrow * 64 + d] = pack_hl(w);
                        ((uint32_t*)g_qsw)[hrow * 64 + d] = pack_lh(w);
                    } else if (mat == 1) {
                        ((uint32_t*)g_ks)[hrow * 64 + d] = pack_hl(v);
                    } else {
                        g_v[hrow * DH_ + d] = v;
                    }
                }
            }
            __syncwarp();
        }
    }
}

// ---------------- WMMA attention — identical to R14 (best known) ----------
#define QB2  16
#define LD_K 136
#define LD_V 264
#define OFF_AN   34816
#define OFF_AW   (OFF_AN + QB2*LD_V*2)   // 43264
#define OFF_RED  (OFF_AW + QB2*LD_V*2)   // 51712
#define SM2_BYTES (OFF_RED + 8192)       // 59904

__global__ __launch_bounds__(256)
void attn_wmma(float* __restrict__ attn_out)
{
    extern __shared__ char smraw[];
    __nv_bfloat16* bB  = (__nv_bfloat16*)smraw;
    __nv_bfloat16* bAn = (__nv_bfloat16*)(smraw + OFF_AN);
    __nv_bfloat16* bAw = (__nv_bfloat16*)(smraw + OFF_AW);
    float* red = (float*)(smraw + OFF_RED);

    const int q0 = blockIdx.x * QB2;
    const int hh = blockIdx.y, bb = blockIdx.z;
    const int tid = threadIdx.x, wid = tid >> 5, lane = tid & 31;
    const int bh = bb * H_ + hh;

    const __nv_bfloat16* Qn = g_qs  + ((size_t)bh * L_ + q0) * 128;
    const __nv_bfloat16* Qw = g_qsw + ((size_t)bh * L_ + q0) * 128;
    const __nv_bfloat16* Kh = g_ks  + (size_t)bh * L_ * 128;
    const __nv_bfloat16* Vt = g_vs  + (size_t)bh * DH_ * (2 * L_);
    float* gW = attn_out + ((size_t)bh * L_ + q0) * L_;   // 16 x 2048 block

    // load Q tiles (16 x 128 bf16 each) into bAn/bAw, ldm LD_K
    for (int u = tid; u < 512; u += 256) {
        int half = u >> 8;
        int v = u & 255;
        int r = v >> 4, q = v & 15;
        uint4 src = ((const uint4*)((half ? Qw : Qn) + r * 128))[q];
        __nv_bfloat16* dst = half ? bAw : bAn;
        *(uint4*)(dst + r * LD_K + q * 8) = src;
    }

    // ---- phase 1: scores -> attn_out (raw) ----
    {
        wmma::fragment<wmma::accumulator, 16, 16, 16, float> sacc;
        for (int kc = 0; kc < L_; kc += 128) {
            __syncthreads();
            #pragma unroll
            for (int i = 0; i < 8; i++) {
                int u = tid + i * 256;           // 2048 uint4
                int r = u >> 4, q = u & 15;
                *(uint4*)(bB + r * LD_K + q * 8) =
                    ((const uint4*)(Kh + (size_t)(kc + r) * 128))[q];
            }
            __syncthreads();
            wmma::fill_fragment(sacc, 0.0f);
            #pragma unroll
            for (int kt = 0; kt < 8; kt++) {
                wmma::fragment<wmma::matrix_a, 16, 16, 16, __nv_bfloat16,
                               wmma::row_major> a;
                wmma::fragment<wmma::matrix_b, 16, 16, 16, __nv_bfloat16,
                               wmma::col_major> b;
                wmma::load_matrix_sync(b, bB + (size_t)wid * 16 * LD_K + kt * 16, LD_K);
                wmma::load_matrix_sync(a, bAn + kt * 16, LD_K);
                wmma::mma_sync(sacc, a, b, sacc);
                wmma::load_matrix_sync(a, bAw + kt * 16, LD_K);
                wmma::mma_sync(sacc, a, b, sacc);
            }
            wmma::store_matrix_sync(gW + kc + wid * 16, sacc, L_,
                                    wmma::mem_row_major);
        }
    }
    __syncthreads();

    // ---- phase 2: softmax in gmem (L2-hot) ----
    for (int r = wid; r < QB2; r += 8) {
        float* row = gW + (size_t)r * L_;
        float m = -1e30f;
        for (int k = lane; k < L_; k += 32) m = fmaxf(m, row[k]);
        #pragma unroll
        for (int o = 16; o; o >>= 1) m = fmaxf(m, __shfl_xor_sync(0xffffffffu, m, o));
        float s = 0.f;
        for (int k = lane; k < L_; k += 32) {
            float e = __expf(row[k] - m);
            row[k] = e;
            s += e;
        }
        #pragma unroll
        for (int o = 16; o; o >>= 1) s += __shfl_xor_sync(0xffffffffu, s, o);
        float inv = 1.f / s;
        for (int k = lane; k < L_; k += 32)
            row[k] = row[k] * inv;
    }
    __syncthreads();

    // ---- phase 3: ctx = W @ V, pack straight into g_cs ----
    {
        wmma::fragment<wmma::accumulator, 16, 16, 16, float> cacc;
        wmma::fill_fragment(cacc, 0.0f);
        const int nt = wid >> 1, kh = wid & 1;
        const int wr2 = tid >> 4, wks = (tid & 15) * 8;
        for (int c = 0; c < 16; c++) {               // 16 chunks x 128 keys
            __syncthreads();
            // Vt chunk [64][256 bf16] -> bB, ldm LD_V
            #pragma unroll
            for (int i = 0; i < 8; i++) {
                int u = tid + i * 256;               // 2048 uint4
                int r = u >> 5, q = u & 31;
                *(uint4*)(bB + r * LD_V + q * 8) =
                    ((const uint4*)(Vt + (size_t)r * (2 * L_) + c * 256))[q];
            }
            // W chunk (gmem weights) -> bAn (hi,lo), bAw (lo,hi): 16 x 128
            {
                const float* srow = gW + (size_t)wr2 * L_ + c * 128 + wks;
                uint32_t* wn = (uint32_t*)bAn + wr2 * (LD_V / 2) + wks;
                uint32_t* ww = (uint32_t*)bAw + wr2 * (LD_V / 2) + wks;
                #pragma unroll
                for (int j = 0; j < 8; j++) {
                    float w = srow[j];
                    wn[j] = pack_hl(w);
                    ww[j] = pack_lh(w);
                }
            }
            __syncthreads();
            #pragma unroll
            for (int kt = 0; kt < 8; kt++) {
                int k0 = kh * 128 + kt * 16;
                wmma::fragment<wmma::matrix_a, 16, 16, 16, __nv_bfloat16,
                               wmma::row_major> a;
                wmma::fragment<wmma::matrix_b, 16, 16, 16, __nv_bfloat16,
                               wmma::col_major> b;
                wmma::load_matrix_sync(b, bB + (size_t)nt * 16 * LD_V + k0, LD_V);
                wmma::load_matrix_sync(a, bAn + k0, LD_V);
                wmma::mma_sync(cacc, a, b, cacc);
                wmma::load_matrix_sync(a, bAw + k0, LD_V);
                wmma::mma_sync(cacc, a, b, cacc);
            }
        }
        __syncthreads();
        wmma::store_matrix_sync(red + wid * 256, cacc, 16, wmma::mem_row_major);
        __syncthreads();
        for (int e = tid; e < QB2 * 64; e += 256) {
            int m = e >> 6, col = e & 63;
            int w0 = (col >> 4) << 1;
            float v = red[w0 * 256 + m * 16 + (col & 15)]
                    + red[(w0 + 1) * 256 + m * 16 + (col & 15)];
            size_t row = (size_t)bb * L_ + q0 + m;
            ((uint32_t*)g_cs)[row * 1024 + hh * 64 + col] = pack_hl(v);
        }
    }
}

// ---------------- launch ----------------
extern "C" void kernel_launch(void* const* d_in, const int* in_sizes, int n_in,
                              void* d_out, int out_size)
{
    const float* x  = (const float*)d_in[0];
    const float* Wq = (const float*)d_in[1];
    const float* bq = (const float*)d_in[2];
    const float* Wk = (const float*)d_in[3];
    const float* bk = (const float*)d_in[4];
    const float* Wv = (const float*)d_in[5];
    const float* bv = (const float*)d_in[6];
    const float* Wo = (const float*)d_in[7];
    const float* bo = (const float*)d_in[8];

    float* out  = (float*)d_out;                       // [B, L, D]
    float* attn = out + (size_t)M_ * D_;               // [B, H, L, L]

    cudaFuncSetAttribute(attn_wmma,
                         cudaFuncAttributeMaxDynamicSharedMemorySize, SM2_BYTES);
    cudaFuncSetAttribute(mma_gemm,
                         cudaFuncAttributeMaxDynamicSharedMemorySize, GSM_BYTES);

    // split projection inputs
    {
        int n4x = M_ * D_ / 4;
        int n4w = D_ * D_ / 4;
        split_x<<<(n4x + 255) / 256, 256>>>(x, n4x);
        split_w<<<(n4w + 255) / 256, 256>>>(Wq, 0, n4w);
        split_w<<<(n4w + 255) / 256, 256>>>(Wk, 1, n4w);
        split_w<<<(n4w + 255) / 256, 256>>>(Wv, 2, n4w);
        split_w<<<(n4w + 255) / 256, 256>>>(Wo, 3, n4w);
    }

    // QKV projections (epilogue writes split Q/K directly; V as float)
    dim3 gq(M_ / TM, D_ / TN, 3);
    mma_gemm<<<gq, 256, GSM_BYTES>>>(0, bq, bk, bv, nullptr);

    // V transpose+split
    dim3 gv(L_ / 128, B_ * H_);
    v_split<<<gv, 256>>>();

    // attention (epilogue packs ctx straight into g_cs)
    dim3 ga(L_ / QB2, H_, B_);
    attn_wmma<<<ga, 256, SM2_BYTES>>>(attn);

    // output projection
    dim3 go(M_ / TM, D_ / TN, 1);
    mma_gemm<<<go, 256, GSM_BYTES>>>(1, bo, bo, bo, out);
}